// round 1
// baseline (speedup 1.0000x reference)
#include <cuda_runtime.h>
#include <cuda_bf16.h>

#define NN 40000
#define EE 640000
#define DH 128

// ---------------- scratch (device globals; no allocation) ----------------
__device__ int   g_cnt[NN];        // histogram / scatter cursor
__device__ int   g_off[NN + 1];    // CSR offsets (by dst)
__device__ int   g_bsum[64];
__device__ int   g_boff[64];
__device__ int   g_esrc[EE];       // src node per edge, grouped by dst, sorted
__device__ float g_y[NN * DH];     // x @ Wl   (pre-aggregation transform)
__device__ float g_z[NN * DH];     // x @ Wr + b
__device__ float g_h[NN * DH];     // layer activations

// ---------------- CSR build ----------------
__global__ void k_zero_cnt() {
    int i = blockIdx.x * blockDim.x + threadIdx.x;
    if (i < NN) g_cnt[i] = 0;
}

__global__ void k_hist(const int* __restrict__ dst) {
    int e = blockIdx.x * blockDim.x + threadIdx.x;
    if (e < EE) atomicAdd(&g_cnt[dst[e]], 1);
}

// block-level scan over 1024 elements; writes local-exclusive offsets + block sums
__global__ void k_scan1() {
    __shared__ int wsum[32];
    int tid = threadIdx.x, lane = tid & 31, w = tid >> 5;
    int i = blockIdx.x * 1024 + tid;
    int v = (i < NN) ? g_cnt[i] : 0;
    int s = v;
#pragma unroll
    for (int o = 1; o < 32; o <<= 1) {
        int t = __shfl_up_sync(0xffffffffu, s, o);
        if (lane >= o) s += t;
    }
    if (lane == 31) wsum[w] = s;
    __syncthreads();
    if (w == 0) {
        int ws = wsum[lane];
        int ss = ws;
#pragma unroll
        for (int o = 1; o < 32; o <<= 1) {
            int t = __shfl_up_sync(0xffffffffu, ss, o);
            if (lane >= o) ss += t;
        }
        wsum[lane] = ss - ws;   // exclusive warp offset
    }
    __syncthreads();
    int incl = s + wsum[w];
    if (i < NN) g_off[i] = incl - v;          // block-local exclusive
    if (tid == 1023) g_bsum[blockIdx.x] = incl;
}

__global__ void k_scan2() {  // 64 threads scan <=64 block sums
    __shared__ int sh[64];
    int t = threadIdx.x;
    int nblk = (NN + 1023) / 1024;
    int v = (t < nblk) ? g_bsum[t] : 0;
    sh[t] = v;
    __syncthreads();
    for (int o = 1; o < 64; o <<= 1) {
        int add = (t >= o) ? sh[t - o] : 0;
        __syncthreads();
        sh[t] += add;
        __syncthreads();
    }
    if (t < nblk) g_boff[t] = sh[t] - v;      // exclusive
}

__global__ void k_scan3() {
    int i = blockIdx.x * blockDim.x + threadIdx.x;
    if (i < NN) g_off[i] += g_boff[i >> 10];
    if (i == 0) g_off[NN] = EE;
}

__global__ void k_scatter(const int* __restrict__ src, const int* __restrict__ dst) {
    int e = blockIdx.x * blockDim.x + threadIdx.x;
    if (e < EE) {
        int d = dst[e];
        int p = atomicAdd(&g_cnt[d], 1);
        g_esrc[g_off[d] + p] = src[e];
    }
}

// sort each node's edge list ascending -> deterministic fp summation order
__global__ void k_sortseg() {
    int n = blockIdx.x * blockDim.x + threadIdx.x;
    if (n >= NN) return;
    int b = g_off[n], e = g_off[n + 1];
    for (int i = b + 1; i < e; i++) {
        int key = g_esrc[i];
        int j = i - 1;
        while (j >= b && g_esrc[j] > key) { g_esrc[j + 1] = g_esrc[j]; j--; }
        g_esrc[j + 1] = key;
    }
}

// ---------------- dual GEMM:  y = X@Wl ;  z = X@Wr + bias ----------------
// X: [NN,128] row-major, Wl/Wr: [128,NOUT] row-major.
// BM=128, BN=64 (per grid.y tile), BK=16, 256 threads, TM=8, TN=4 per output.
__global__ void __launch_bounds__(256) k_gemm(
    const float* __restrict__ X, const float* __restrict__ Wl,
    const float* __restrict__ Wr, const float* __restrict__ bias, int NOUT)
{
    __shared__ __align__(16) float As[16][132];  // transposed A tile (pad 4)
    __shared__ __align__(16) float Ls[16][64];
    __shared__ __align__(16) float Rs[16][64];

    int m0 = blockIdx.x * 128;
    int n0 = blockIdx.y * 64;
    int tid = threadIdx.x;
    int tr = tid >> 4;        // 0..15 row group
    int tc = tid & 15;        // 0..15 col group

    float accY[8][4];
    float accZ[8][4];
#pragma unroll
    for (int i = 0; i < 8; i++)
#pragma unroll
        for (int j = 0; j < 4; j++) { accY[i][j] = 0.f; accZ[i][j] = 0.f; }

    for (int k0 = 0; k0 < 128; k0 += 16) {
        // load A tile 128x16 (512 float4, 2 per thread), store transposed
#pragma unroll
        for (int it = 0; it < 2; it++) {
            int idx = tid + it * 256;
            int r = idx >> 2, c4 = idx & 3;
            int gr = m0 + r;
            float4 v = make_float4(0.f, 0.f, 0.f, 0.f);
            if (gr < NN) v = *(const float4*)&X[gr * 128 + k0 + c4 * 4];
            As[c4 * 4 + 0][r] = v.x;
            As[c4 * 4 + 1][r] = v.y;
            As[c4 * 4 + 2][r] = v.z;
            As[c4 * 4 + 3][r] = v.w;
        }
        // load weight tiles 16x64 (256 float4 each, 1 per thread)
        {
            int kr = tid >> 4, c4 = tid & 15;
            *(float4*)&Ls[kr][c4 * 4] = *(const float4*)&Wl[(k0 + kr) * NOUT + n0 + c4 * 4];
            *(float4*)&Rs[kr][c4 * 4] = *(const float4*)&Wr[(k0 + kr) * NOUT + n0 + c4 * 4];
        }
        __syncthreads();
#pragma unroll
        for (int k = 0; k < 16; k++) {
            float4 a0 = *(float4*)&As[k][tr * 8];
            float4 a1 = *(float4*)&As[k][tr * 8 + 4];
            float4 wl = *(float4*)&Ls[k][tc * 4];
            float4 wr = *(float4*)&Rs[k][tc * 4];
            float a[8] = {a0.x, a0.y, a0.z, a0.w, a1.x, a1.y, a1.z, a1.w};
            float l[4] = {wl.x, wl.y, wl.z, wl.w};
            float r[4] = {wr.x, wr.y, wr.z, wr.w};
#pragma unroll
            for (int i = 0; i < 8; i++)
#pragma unroll
                for (int j = 0; j < 4; j++) {
                    accY[i][j] += a[i] * l[j];
                    accZ[i][j] += a[i] * r[j];
                }
        }
        __syncthreads();
    }

    float4 b4 = *(const float4*)&bias[n0 + tc * 4];
    float bb[4] = {b4.x, b4.y, b4.z, b4.w};
#pragma unroll
    for (int i = 0; i < 8; i++) {
        int gr = m0 + tr * 8 + i;
        if (gr < NN) {
            float4 oy = make_float4(accY[i][0], accY[i][1], accY[i][2], accY[i][3]);
            float4 oz = make_float4(accZ[i][0] + bb[0], accZ[i][1] + bb[1],
                                    accZ[i][2] + bb[2], accZ[i][3] + bb[3]);
            *(float4*)&g_y[gr * NOUT + n0 + tc * 4] = oy;
            *(float4*)&g_z[gr * NOUT + n0 + tc * 4] = oz;
        }
    }
}

// ---------------- aggregation + relu + LayerNorm (NOUT=128) ----------------
// one warp per node; lane owns 4 features (float4)
__global__ void __launch_bounds__(256) k_agg_ln(
    const float* __restrict__ gamma, const float* __restrict__ beta)
{
    int w = threadIdx.x >> 5, lane = threadIdx.x & 31;
    int n = blockIdx.x * 8 + w;
    if (n >= NN) return;
    int beg = g_off[n], end = g_off[n + 1];
    float4 acc = make_float4(0.f, 0.f, 0.f, 0.f);
#pragma unroll 4
    for (int e = beg; e < end; e++) {
        int s = g_esrc[e];
        float4 v = *(const float4*)&g_y[s * 128 + lane * 4];
        acc.x += v.x; acc.y += v.y; acc.z += v.z; acc.w += v.w;
    }
    int cnt = end - beg;
    float inv = 1.f / (float)max(cnt, 1);
    float4 z = *(const float4*)&g_z[n * 128 + lane * 4];
    float v0 = fmaxf(fmaf(acc.x, inv, z.x), 0.f);
    float v1 = fmaxf(fmaf(acc.y, inv, z.y), 0.f);
    float v2 = fmaxf(fmaf(acc.z, inv, z.z), 0.f);
    float v3 = fmaxf(fmaf(acc.w, inv, z.w), 0.f);

    float s1 = v0 + v1 + v2 + v3;
    float s2 = v0 * v0 + v1 * v1 + v2 * v2 + v3 * v3;
#pragma unroll
    for (int o = 16; o > 0; o >>= 1) {
        s1 += __shfl_xor_sync(0xffffffffu, s1, o);
        s2 += __shfl_xor_sync(0xffffffffu, s2, o);
    }
    float mu = s1 * (1.f / 128.f);
    float var = s2 * (1.f / 128.f) - mu * mu;
    float rs = rsqrtf(var + 1e-5f);
    float4 g4 = *(const float4*)&gamma[lane * 4];
    float4 be = *(const float4*)&beta[lane * 4];
    float4 o;
    o.x = (v0 - mu) * rs * g4.x + be.x;
    o.y = (v1 - mu) * rs * g4.y + be.y;
    o.z = (v2 - mu) * rs * g4.z + be.z;
    o.w = (v3 - mu) * rs * g4.w + be.w;
    *(float4*)&g_h[n * 128 + lane * 4] = o;
}

// ---------------- final aggregation (NOUT=64, no relu/LN) ----------------
__global__ void __launch_bounds__(256) k_agg_out(float* __restrict__ out)
{
    int w = threadIdx.x >> 5, lane = threadIdx.x & 31;
    int n = blockIdx.x * 8 + w;
    if (n >= NN) return;
    int beg = g_off[n], end = g_off[n + 1];
    float2 acc = make_float2(0.f, 0.f);
#pragma unroll 4
    for (int e = beg; e < end; e++) {
        int s = g_esrc[e];
        float2 v = *(const float2*)&g_y[s * 64 + lane * 2];
        acc.x += v.x; acc.y += v.y;
    }
    int cnt = end - beg;
    float inv = 1.f / (float)max(cnt, 1);
    float2 z = *(const float2*)&g_z[n * 64 + lane * 2];
    float2 o;
    o.x = fmaf(acc.x, inv, z.x);
    o.y = fmaf(acc.y, inv, z.y);
    *(float2*)&out[n * 64 + lane * 2] = o;
}

// ---------------- launch ----------------
extern "C" void kernel_launch(void* const* d_in, const int* in_sizes, int n_in,
                              void* d_out, int out_size)
{
    const float* x   = (const float*)d_in[0];
    const int*   ei  = (const int*)d_in[1];
    const float* Wl0 = (const float*)d_in[2];
    const float* bl0 = (const float*)d_in[3];
    const float* Wr0 = (const float*)d_in[4];
    const float* Wl1 = (const float*)d_in[5];
    const float* bl1 = (const float*)d_in[6];
    const float* Wr1 = (const float*)d_in[7];
    const float* Wl2 = (const float*)d_in[8];
    const float* bl2 = (const float*)d_in[9];
    const float* Wr2 = (const float*)d_in[10];
    const float* g0  = (const float*)d_in[11];
    const float* b0  = (const float*)d_in[12];
    const float* g1  = (const float*)d_in[13];
    const float* b1  = (const float*)d_in[14];
    float* out = (float*)d_out;

    const int* src = ei;
    const int* dst = ei + EE;

    float* hptr = nullptr;
    cudaGetSymbolAddress((void**)&hptr, g_h);

    const int NB_N = (NN + 255) / 256;   // 157
    const int NB_E = (EE + 255) / 256;   // 2500
    const int NB_SCAN = (NN + 1023) / 1024;  // 40

    // CSR build (by dst)
    k_zero_cnt<<<NB_N, 256>>>();
    k_hist<<<NB_E, 256>>>(dst);
    k_scan1<<<NB_SCAN, 1024>>>();
    k_scan2<<<1, 64>>>();
    k_scan3<<<NB_N, 256>>>();
    k_zero_cnt<<<NB_N, 256>>>();
    k_scatter<<<NB_E, 256>>>(src, dst);
    k_sortseg<<<NB_N, 256>>>();

    dim3 gemm_grid_128((NN + 127) / 128, 2);
    dim3 gemm_grid_64((NN + 127) / 128, 1);
    const int NB_AGG = (NN + 7) / 8;     // 5000

    // layer 0
    k_gemm<<<gemm_grid_128, 256>>>(x, Wl0, Wr0, bl0, 128);
    k_agg_ln<<<NB_AGG, 256>>>(g0, b0);
    // layer 1
    k_gemm<<<gemm_grid_128, 256>>>(hptr, Wl1, Wr1, bl1, 128);
    k_agg_ln<<<NB_AGG, 256>>>(g1, b1);
    // layer 2
    k_gemm<<<gemm_grid_64, 256>>>(hptr, Wl2, Wr2, bl2, 64);
    k_agg_out<<<NB_AGG, 256>>>(out);
}

// round 4
// speedup vs baseline: 1.3451x; 1.3451x over previous
#include <cuda_runtime.h>
#include <cstdint>

#define NN 40000
#define EE 640000

// ---------------- scratch (device globals; no allocation) ----------------
__device__ int   g_cnt[NN];
__device__ int   g_off[NN + 1];
__device__ int   g_bsum[64];
__device__ int   g_boff[64];
__device__ int   g_esrc[EE];
__device__ float g_y[NN * 128];
__device__ float g_z[NN * 128];
__device__ float g_h[NN * 128];

// ---------------- CSR build ----------------
__global__ void k_zero_cnt() {
    int i = blockIdx.x * blockDim.x + threadIdx.x;
    if (i < NN) g_cnt[i] = 0;
}

__global__ void k_hist(const int* __restrict__ dst) {
    int e = blockIdx.x * blockDim.x + threadIdx.x;
    if (e < EE) atomicAdd(&g_cnt[dst[e]], 1);
}

__global__ void k_scan1() {
    __shared__ int wsum[32];
    int tid = threadIdx.x, lane = tid & 31, w = tid >> 5;
    int i = blockIdx.x * 1024 + tid;
    int v = (i < NN) ? g_cnt[i] : 0;
    int s = v;
#pragma unroll
    for (int o = 1; o < 32; o <<= 1) {
        int t = __shfl_up_sync(0xffffffffu, s, o);
        if (lane >= o) s += t;
    }
    if (lane == 31) wsum[w] = s;
    __syncthreads();
    if (w == 0) {
        int ws = wsum[lane];
        int ss = ws;
#pragma unroll
        for (int o = 1; o < 32; o <<= 1) {
            int t = __shfl_up_sync(0xffffffffu, ss, o);
            if (lane >= o) ss += t;
        }
        wsum[lane] = ss - ws;
    }
    __syncthreads();
    int incl = s + wsum[w];
    if (i < NN) g_off[i] = incl - v;
    if (tid == 1023) g_bsum[blockIdx.x] = incl;
}

__global__ void k_scan2() {
    __shared__ int sh[64];
    int t = threadIdx.x;
    int nblk = (NN + 1023) / 1024;
    int v = (t < nblk) ? g_bsum[t] : 0;
    sh[t] = v;
    __syncthreads();
    for (int o = 1; o < 64; o <<= 1) {
        int add = (t >= o) ? sh[t - o] : 0;
        __syncthreads();
        sh[t] += add;
        __syncthreads();
    }
    if (t < nblk) g_boff[t] = sh[t] - v;
}

__global__ void k_scan3() {
    int i = blockIdx.x * blockDim.x + threadIdx.x;
    if (i < NN) g_off[i] += g_boff[i >> 10];
    if (i == 0) g_off[NN] = EE;
}

__global__ void k_scatter(const int* __restrict__ src, const int* __restrict__ dst) {
    int e = blockIdx.x * blockDim.x + threadIdx.x;
    if (e < EE) {
        int d = dst[e];
        int p = atomicAdd(&g_cnt[d], 1);
        g_esrc[g_off[d] + p] = src[e];
    }
}

__global__ void k_sortseg() {
    int n = blockIdx.x * blockDim.x + threadIdx.x;
    if (n >= NN) return;
    int b = g_off[n], e = g_off[n + 1];
    for (int i = b + 1; i < e; i++) {
        int key = g_esrc[i];
        int j = i - 1;
        while (j >= b && g_esrc[j] > key) { g_esrc[j + 1] = g_esrc[j]; j--; }
        g_esrc[j + 1] = key;
    }
}

// ---------------- warp-MMA tf32 dual GEMM ----------------
__device__ __forceinline__ uint32_t to_tf32(float x) {
    uint32_t r;
    asm("cvt.rna.tf32.f32 %0, %1;" : "=r"(r) : "f"(x));
    return r;
}

__device__ __forceinline__ void mma_tf32(float* d, const uint32_t* a, const uint32_t* b) {
    asm volatile(
        "mma.sync.aligned.m16n8k8.row.col.f32.tf32.tf32.f32 "
        "{%0,%1,%2,%3}, {%4,%5,%6,%7}, {%8,%9}, {%0,%1,%2,%3};"
        : "+f"(d[0]), "+f"(d[1]), "+f"(d[2]), "+f"(d[3])
        : "r"(a[0]), "r"(a[1]), "r"(a[2]), "r"(a[3]),
          "r"(b[0]), "r"(b[1]));
}

// C = X[128 rows] @ [Wl | Wr]  over a 128-wide N slice (grid.y picks slice).
// Epilogue: global col < NOUT -> g_y ; else -> g_z + bias.
// A smem: 128 x 132 u32 (pad -> conflict-free frag loads)
// B smem: 128(k) x 136 u32
#define ASTR 132
#define BSTR 136

__global__ void __launch_bounds__(256) k_mmagemm(
    const float* __restrict__ X, const float* __restrict__ Wl,
    const float* __restrict__ Wr, const float* __restrict__ bias,
    float* __restrict__ Y, float* __restrict__ Z, int NOUT)
{
    extern __shared__ __align__(16) uint32_t sm[];
    uint32_t* As = sm;                 // [m][k]
    uint32_t* Bs = sm + 128 * ASTR;    // [k][n]

    int tid = threadIdx.x;
    int wid = tid >> 5, lane = tid & 31;
    int gid = lane >> 2, tig = lane & 3;
    int wm = wid & 3, wn = wid >> 2;   // 4 x 2 warp grid
    int m0 = blockIdx.x * 128;
    int n0 = blockIdx.y * 128;

    // ---- global -> smem, cvt tf32 ----
    // A: 128x128 floats, 16 float4 per thread
#pragma unroll
    for (int it = 0; it < 16; it++) {
        int idx = tid + it * 256;      // float4 index
        int m = idx >> 5;
        int k4 = (idx & 31) * 4;
        float4 v = make_float4(0.f, 0.f, 0.f, 0.f);
        if (m0 + m < NN) v = *(const float4*)&X[(size_t)(m0 + m) * 128 + k4];
        uint32_t* p = &As[m * ASTR + k4];
        p[0] = to_tf32(v.x); p[1] = to_tf32(v.y);
        p[2] = to_tf32(v.z); p[3] = to_tf32(v.w);
    }
    // B: 128(k) x 128(n) floats; col n_glob = n0 + nl ; split Wl/Wr halves
#pragma unroll
    for (int it = 0; it < 16; it++) {
        int idx = tid + it * 256;
        int k = idx >> 5;
        int nl4 = (idx & 31) * 4;
        int ng = n0 + nl4;
        float4 v;
        if (ng < NOUT) v = *(const float4*)&Wl[(size_t)k * NOUT + ng];
        else           v = *(const float4*)&Wr[(size_t)k * NOUT + (ng - NOUT)];
        uint32_t* p = &Bs[k * BSTR + nl4];
        p[0] = to_tf32(v.x); p[1] = to_tf32(v.y);
        p[2] = to_tf32(v.z); p[3] = to_tf32(v.w);
    }
    __syncthreads();

    float acc[2][8][4];
#pragma unroll
    for (int mi = 0; mi < 2; mi++)
#pragma unroll
        for (int nf = 0; nf < 8; nf++)
#pragma unroll
            for (int j = 0; j < 4; j++) acc[mi][nf][j] = 0.f;

#pragma unroll
    for (int k0 = 0; k0 < 128; k0 += 8) {
        uint32_t a[2][4];
#pragma unroll
        for (int mi = 0; mi < 2; mi++) {
            int r = wm * 32 + mi * 16;
            a[mi][0] = As[(r + gid) * ASTR + k0 + tig];
            a[mi][1] = As[(r + gid + 8) * ASTR + k0 + tig];
            a[mi][2] = As[(r + gid) * ASTR + k0 + tig + 4];
            a[mi][3] = As[(r + gid + 8) * ASTR + k0 + tig + 4];
        }
        uint32_t b[8][2];
#pragma unroll
        for (int nf = 0; nf < 8; nf++) {
            int n = wn * 64 + nf * 8 + gid;
            b[nf][0] = Bs[(k0 + tig) * BSTR + n];
            b[nf][1] = Bs[(k0 + tig + 4) * BSTR + n];
        }
#pragma unroll
        for (int mi = 0; mi < 2; mi++)
#pragma unroll
            for (int nf = 0; nf < 8; nf++)
                mma_tf32(acc[mi][nf], a[mi], b[nf]);
    }

    // ---- epilogue ----
#pragma unroll
    for (int mi = 0; mi < 2; mi++) {
#pragma unroll
        for (int nf = 0; nf < 8; nf++) {
            int col = n0 + wn * 64 + nf * 8 + 2 * tig;
            int r0 = m0 + wm * 32 + mi * 16 + gid;
            int r1 = r0 + 8;
            if (col < NOUT) {
                if (r0 < NN) { float2 o = {acc[mi][nf][0], acc[mi][nf][1]};
                               *(float2*)&Y[(size_t)r0 * NOUT + col] = o; }
                if (r1 < NN) { float2 o = {acc[mi][nf][2], acc[mi][nf][3]};
                               *(float2*)&Y[(size_t)r1 * NOUT + col] = o; }
            } else {
                int c = col - NOUT;
                float2 b2 = *(const float2*)&bias[c];
                if (r0 < NN) { float2 o = {acc[mi][nf][0] + b2.x, acc[mi][nf][1] + b2.y};
                               *(float2*)&Z[(size_t)r0 * NOUT + c] = o; }
                if (r1 < NN) { float2 o = {acc[mi][nf][2] + b2.x, acc[mi][nf][3] + b2.y};
                               *(float2*)&Z[(size_t)r1 * NOUT + c] = o; }
            }
        }
    }
}

// ---------------- aggregation + relu + LayerNorm (dim 128) ----------------
__global__ void __launch_bounds__(256) k_agg_ln(
    const float* __restrict__ gamma, const float* __restrict__ beta)
{
    int w = threadIdx.x >> 5, lane = threadIdx.x & 31;
    int n = blockIdx.x * 8 + w;
    if (n >= NN) return;
    int beg = g_off[n], end = g_off[n + 1];
    float4 acc = make_float4(0.f, 0.f, 0.f, 0.f);
#pragma unroll 4
    for (int e = beg; e < end; e++) {
        int s = g_esrc[e];
        float4 v = *(const float4*)&g_y[(size_t)s * 128 + lane * 4];
        acc.x += v.x; acc.y += v.y; acc.z += v.z; acc.w += v.w;
    }
    int cnt = end - beg;
    float inv = 1.f / (float)max(cnt, 1);
    float4 z = *(const float4*)&g_z[(size_t)n * 128 + lane * 4];
    float v0 = fmaxf(fmaf(acc.x, inv, z.x), 0.f);
    float v1 = fmaxf(fmaf(acc.y, inv, z.y), 0.f);
    float v2 = fmaxf(fmaf(acc.z, inv, z.z), 0.f);
    float v3 = fmaxf(fmaf(acc.w, inv, z.w), 0.f);

    float s1 = v0 + v1 + v2 + v3;
    float s2 = v0 * v0 + v1 * v1 + v2 * v2 + v3 * v3;
#pragma unroll
    for (int o = 16; o > 0; o >>= 1) {
        s1 += __shfl_xor_sync(0xffffffffu, s1, o);
        s2 += __shfl_xor_sync(0xffffffffu, s2, o);
    }
    float mu = s1 * (1.f / 128.f);
    float var = s2 * (1.f / 128.f) - mu * mu;
    float rs = rsqrtf(var + 1e-5f);
    float4 g4 = *(const float4*)&gamma[lane * 4];
    float4 be = *(const float4*)&beta[lane * 4];
    float4 o;
    o.x = (v0 - mu) * rs * g4.x + be.x;
    o.y = (v1 - mu) * rs * g4.y + be.y;
    o.z = (v2 - mu) * rs * g4.z + be.z;
    o.w = (v3 - mu) * rs * g4.w + be.w;
    *(float4*)&g_h[(size_t)n * 128 + lane * 4] = o;
}

// ---------------- final aggregation (dim 64) ----------------
__global__ void __launch_bounds__(256) k_agg_out(float* __restrict__ out)
{
    int w = threadIdx.x >> 5, lane = threadIdx.x & 31;
    int n = blockIdx.x * 8 + w;
    if (n >= NN) return;
    int beg = g_off[n], end = g_off[n + 1];
    float2 acc = make_float2(0.f, 0.f);
#pragma unroll 4
    for (int e = beg; e < end; e++) {
        int s = g_esrc[e];
        float2 v = *(const float2*)&g_y[(size_t)s * 64 + lane * 2];
        acc.x += v.x; acc.y += v.y;
    }
    int cnt = end - beg;
    float inv = 1.f / (float)max(cnt, 1);
    float2 z = *(const float2*)&g_z[(size_t)n * 64 + lane * 2];
    float2 o;
    o.x = fmaf(acc.x, inv, z.x);
    o.y = fmaf(acc.y, inv, z.y);
    *(float2*)&out[(size_t)n * 64 + lane * 2] = o;
}

// ---------------- launch ----------------
extern "C" void kernel_launch(void* const* d_in, const int* in_sizes, int n_in,
                              void* d_out, int out_size)
{
    const float* x   = (const float*)d_in[0];
    const int*   ei  = (const int*)d_in[1];
    const float* Wl0 = (const float*)d_in[2];
    const float* bl0 = (const float*)d_in[3];
    const float* Wr0 = (const float*)d_in[4];
    const float* Wl1 = (const float*)d_in[5];
    const float* bl1 = (const float*)d_in[6];
    const float* Wr1 = (const float*)d_in[7];
    const float* Wl2 = (const float*)d_in[8];
    const float* bl2 = (const float*)d_in[9];
    const float* Wr2 = (const float*)d_in[10];
    const float* g0  = (const float*)d_in[11];
    const float* b0  = (const float*)d_in[12];
    const float* g1  = (const float*)d_in[13];
    const float* b1  = (const float*)d_in[14];
    float* out = (float*)d_out;

    const int* src = ei;
    const int* dst = ei + EE;

    float* yptr = nullptr; cudaGetSymbolAddress((void**)&yptr, g_y);
    float* zptr = nullptr; cudaGetSymbolAddress((void**)&zptr, g_z);
    float* hptr = nullptr; cudaGetSymbolAddress((void**)&hptr, g_h);

    const int NB_N = (NN + 255) / 256;
    const int NB_E = (EE + 255) / 256;
    const int NB_SCAN = (NN + 1023) / 1024;

    const int SMEM = (128 * ASTR + 128 * BSTR) * 4;   // 137,216 B
    cudaFuncSetAttribute(k_mmagemm, cudaFuncAttributeMaxDynamicSharedMemorySize, SMEM);

    // CSR build (by dst)
    k_zero_cnt<<<NB_N, 256>>>();
    k_hist<<<NB_E, 256>>>(dst);
    k_scan1<<<NB_SCAN, 1024>>>();
    k_scan2<<<1, 64>>>();
    k_scan3<<<NB_N, 256>>>();
    k_zero_cnt<<<NB_N, 256>>>();
    k_scatter<<<NB_E, 256>>>(src, dst);
    k_sortseg<<<NB_N, 256>>>();

    dim3 grid_h((NN + 127) / 128, 2);   // layers 0/1: N = 256
    dim3 grid_o((NN + 127) / 128, 1);   // layer 2:  N = 128
    const int NB_AGG = (NN + 7) / 8;

    // layer 0
    k_mmagemm<<<grid_h, 256, SMEM>>>(x, Wl0, Wr0, bl0, yptr, zptr, 128);
    k_agg_ln<<<NB_AGG, 256>>>(g0, b0);
    // layer 1
    k_mmagemm<<<grid_h, 256, SMEM>>>(hptr, Wl1, Wr1, bl1, yptr, zptr, 128);
    k_agg_ln<<<NB_AGG, 256>>>(g1, b1);
    // layer 2
    k_mmagemm<<<grid_o, 256, SMEM>>>(hptr, Wl2, Wr2, bl2, yptr, zptr, 64);
    k_agg_out<<<NB_AGG, 256>>>(out);
}

// round 6
// speedup vs baseline: 1.6463x; 1.2239x over previous
#include <cuda_runtime.h>
#include <cstdint>

#define NN 40000
#define EE 640000

// ---------------- scratch (device globals; no allocation) ----------------
__device__ int   g_cnt[NN];
__device__ int   g_off[NN + 1];
__device__ int   g_bsum[64];
__device__ int   g_boff[64];
__device__ int   g_esrc[EE];
__device__ float g_y[NN * 128];
__device__ float g_z[NN * 128];
__device__ float g_h[NN * 128];

// ---------------- CSR build ----------------
__global__ void k_hist(const int* __restrict__ dst) {
    int e = blockIdx.x * blockDim.x + threadIdx.x;
    if (e < EE) atomicAdd(&g_cnt[dst[e]], 1);
}

__global__ void k_scan1() {
    __shared__ int wsum[32];
    int tid = threadIdx.x, lane = tid & 31, w = tid >> 5;
    int i = blockIdx.x * 1024 + tid;
    int v = (i < NN) ? g_cnt[i] : 0;
    int s = v;
#pragma unroll
    for (int o = 1; o < 32; o <<= 1) {
        int t = __shfl_up_sync(0xffffffffu, s, o);
        if (lane >= o) s += t;
    }
    if (lane == 31) wsum[w] = s;
    __syncthreads();
    if (w == 0) {
        int ws = wsum[lane];
        int ss = ws;
#pragma unroll
        for (int o = 1; o < 32; o <<= 1) {
            int t = __shfl_up_sync(0xffffffffu, ss, o);
            if (lane >= o) ss += t;
        }
        wsum[lane] = ss - ws;
    }
    __syncthreads();
    int incl = s + wsum[w];
    if (i < NN) g_off[i] = incl - v;
    if (tid == 1023) g_bsum[blockIdx.x] = incl;
}

__global__ void k_scan2() {
    __shared__ int sh[64];
    int t = threadIdx.x;
    int nblk = (NN + 1023) / 1024;
    int v = (t < nblk) ? g_bsum[t] : 0;
    sh[t] = v;
    __syncthreads();
    for (int o = 1; o < 64; o <<= 1) {
        int add = (t >= o) ? sh[t - o] : 0;
        __syncthreads();
        sh[t] += add;
        __syncthreads();
    }
    if (t < nblk) g_boff[t] = sh[t] - v;
}

// adds block offsets AND resets g_cnt for the scatter pass
__global__ void k_scan3z() {
    int i = blockIdx.x * blockDim.x + threadIdx.x;
    if (i < NN) {
        g_off[i] += g_boff[i >> 10];
        g_cnt[i] = 0;
    }
    if (i == 0) g_off[NN] = EE;
}

__global__ void k_scatter(const int* __restrict__ src, const int* __restrict__ dst) {
    int e = blockIdx.x * blockDim.x + threadIdx.x;
    if (e < EE) {
        int d = dst[e];
        int p = atomicAdd(&g_cnt[d], 1);
        g_esrc[g_off[d] + p] = src[e];
    }
}

// block-cooperative segment sort: 256 nodes/block staged through smem
#define SNODES 256
#define SCAP   10240   // 40KB of int
__global__ void __launch_bounds__(256) k_sortseg2() {
    __shared__ int buf[SCAP];
    int nb = blockIdx.x * SNODES;
    int ne = min(nb + SNODES, NN);
    int beg = g_off[nb], end = g_off[ne];
    int total = end - beg;
    if (total <= SCAP) {
        for (int i = threadIdx.x; i < total; i += 256) buf[i] = g_esrc[beg + i];
        __syncthreads();
        int n = nb + threadIdx.x;
        if (n < ne) {
            int b = g_off[n] - beg, e = g_off[n + 1] - beg;
            for (int i = b + 1; i < e; i++) {
                int key = buf[i];
                int j = i - 1;
                while (j >= b && buf[j] > key) { buf[j + 1] = buf[j]; j--; }
                buf[j + 1] = key;
            }
        }
        __syncthreads();
        for (int i = threadIdx.x; i < total; i += 256) g_esrc[beg + i] = buf[i];
    } else {  // statistically unreachable fallback: sort in global
        int n = nb + threadIdx.x;
        if (n < ne) {
            int b = g_off[n], e = g_off[n + 1];
            for (int i = b + 1; i < e; i++) {
                int key = g_esrc[i];
                int j = i - 1;
                while (j >= b && g_esrc[j] > key) { g_esrc[j + 1] = g_esrc[j]; j--; }
                g_esrc[j + 1] = key;
            }
        }
    }
}

// ---------------- warp-MMA tf32 dual GEMM, BK=16 double-buffered ----------------
__device__ __forceinline__ uint32_t to_tf32(float x) {
    uint32_t r;
    asm("cvt.rna.tf32.f32 %0, %1;" : "=r"(r) : "f"(x));
    return r;
}

__device__ __forceinline__ void mma_tf32(float* d, const uint32_t* a, const uint32_t* b) {
    asm volatile(
        "mma.sync.aligned.m16n8k8.row.col.f32.tf32.tf32.f32 "
        "{%0,%1,%2,%3}, {%4,%5,%6,%7}, {%8,%9}, {%0,%1,%2,%3};"
        : "+f"(d[0]), "+f"(d[1]), "+f"(d[2]), "+f"(d[3])
        : "r"(a[0]), "r"(a[1]), "r"(a[2]), "r"(a[3]),
          "r"(b[0]), "r"(b[1]));
}

#define ASTR 20     // 16 + pad4 -> conflict-free A frag loads
#define BSTR 136    // 128 + pad8 -> conflict-free B frag loads
#define NSTAGE 8    // 128 / BK

__global__ void __launch_bounds__(256, 2) k_mmagemm(
    const float* __restrict__ X, const float* __restrict__ Wl,
    const float* __restrict__ Wr, const float* __restrict__ bias,
    float* __restrict__ Y, float* __restrict__ Z, int NOUT)
{
    __shared__ __align__(16) uint32_t As[2][128 * ASTR];  // [m][k]
    __shared__ __align__(16) uint32_t Bs[2][16 * BSTR];   // [k][n]

    int tid = threadIdx.x;
    int wid = tid >> 5, lane = tid & 31;
    int gid = lane >> 2, tig = lane & 3;
    int wm = wid & 3, wn = wid >> 2;   // 4 x 2 warp grid, warp tile 32x64
    int m0 = blockIdx.x * 128;
    int n0 = blockIdx.y * 128;

    // per-stage load geometry (2 float4 each for A and B per thread)
    // A: 128 rows x 16 k = 512 float4 ; idx = tid + it*256 ; m = idx>>2, k4 = (idx&3)*4
    // B: 16 k x 128 n   = 512 float4 ; k = idx>>5, n4 = (idx&31)*4
    int am[2], ak[2], bk[2], bn[2];
    const float* bsrc[2];
#pragma unroll
    for (int it = 0; it < 2; it++) {
        int idx = tid + it * 256;
        am[it] = idx >> 2;
        ak[it] = (idx & 3) * 4;
        bk[it] = idx >> 5;
        int n4 = (idx & 31) * 4;
        int ng = n0 + n4;
        if (ng < NOUT) { bsrc[it] = Wl + ng; bn[it] = n4; }
        else           { bsrc[it] = Wr + (ng - NOUT); bn[it] = n4; }
    }

    float4 ar[2], br[2];
    auto load_stage = [&](int s) {
#pragma unroll
        for (int it = 0; it < 2; it++) {
            int gr = m0 + am[it];
            ar[it] = (gr < NN) ? *(const float4*)&X[(size_t)gr * 128 + s * 16 + ak[it]]
                               : make_float4(0.f, 0.f, 0.f, 0.f);
            br[it] = *(const float4*)&bsrc[it][(size_t)(s * 16 + bk[it]) * NOUT];
        }
    };
    auto store_stage = [&](int buf) {
#pragma unroll
        for (int it = 0; it < 2; it++) {
            uint32_t* p = &As[buf][am[it] * ASTR + ak[it]];
            uint4 v = make_uint4(to_tf32(ar[it].x), to_tf32(ar[it].y),
                                 to_tf32(ar[it].z), to_tf32(ar[it].w));
            *(uint4*)p = v;
            uint32_t* q = &Bs[buf][bk[it] * BSTR + bn[it]];
            uint4 w = make_uint4(to_tf32(br[it].x), to_tf32(br[it].y),
                                 to_tf32(br[it].z), to_tf32(br[it].w));
            *(uint4*)q = w;
        }
    };

    float acc[2][8][4];
#pragma unroll
    for (int mi = 0; mi < 2; mi++)
#pragma unroll
        for (int nf = 0; nf < 8; nf++)
#pragma unroll
            for (int j = 0; j < 4; j++) acc[mi][nf][j] = 0.f;

    load_stage(0);
    store_stage(0);
    __syncthreads();

#pragma unroll
    for (int s = 0; s < NSTAGE; s++) {
        int buf = s & 1;
        if (s + 1 < NSTAGE) load_stage(s + 1);
        // compute: 2 k-steps of 8 within this stage
#pragma unroll
        for (int kk = 0; kk < 16; kk += 8) {
            uint32_t a[2][4];
#pragma unroll
            for (int mi = 0; mi < 2; mi++) {
                int r = wm * 32 + mi * 16;
                a[mi][0] = As[buf][(r + gid) * ASTR + kk + tig];
                a[mi][1] = As[buf][(r + gid + 8) * ASTR + kk + tig];
                a[mi][2] = As[buf][(r + gid) * ASTR + kk + tig + 4];
                a[mi][3] = As[buf][(r + gid + 8) * ASTR + kk + tig + 4];
            }
            uint32_t b[8][2];
#pragma unroll
            for (int nf = 0; nf < 8; nf++) {
                int n = wn * 64 + nf * 8 + gid;
                b[nf][0] = Bs[buf][(kk + tig) * BSTR + n];
                b[nf][1] = Bs[buf][(kk + tig + 4) * BSTR + n];
            }
#pragma unroll
            for (int mi = 0; mi < 2; mi++)
#pragma unroll
                for (int nf = 0; nf < 8; nf++)
                    mma_tf32(acc[mi][nf], a[mi], b[nf]);
        }
        if (s + 1 < NSTAGE) {
            store_stage(buf ^ 1);
            __syncthreads();
        }
    }

    // ---- epilogue: col < NOUT -> Y ; else -> Z + bias ----
#pragma unroll
    for (int mi = 0; mi < 2; mi++) {
#pragma unroll
        for (int nf = 0; nf < 8; nf++) {
            int col = n0 + wn * 64 + nf * 8 + 2 * tig;
            int r0 = m0 + wm * 32 + mi * 16 + gid;
            int r1 = r0 + 8;
            if (col < NOUT) {
                if (r0 < NN) { float2 o = {acc[mi][nf][0], acc[mi][nf][1]};
                               *(float2*)&Y[(size_t)r0 * NOUT + col] = o; }
                if (r1 < NN) { float2 o = {acc[mi][nf][2], acc[mi][nf][3]};
                               *(float2*)&Y[(size_t)r1 * NOUT + col] = o; }
            } else {
                int c = col - NOUT;
                float2 b2 = *(const float2*)&bias[c];
                if (r0 < NN) { float2 o = {acc[mi][nf][0] + b2.x, acc[mi][nf][1] + b2.y};
                               *(float2*)&Z[(size_t)r0 * NOUT + c] = o; }
                if (r1 < NN) { float2 o = {acc[mi][nf][2] + b2.x, acc[mi][nf][3] + b2.y};
                               *(float2*)&Z[(size_t)r1 * NOUT + c] = o; }
            }
        }
    }
}

// ---------------- aggregation + relu + LayerNorm (dim 128) ----------------
__global__ void __launch_bounds__(256) k_agg_ln(
    const float* __restrict__ gamma, const float* __restrict__ beta)
{
    int w = threadIdx.x >> 5, lane = threadIdx.x & 31;
    int n = blockIdx.x * 8 + w;
    if (n >= NN) return;
    int beg = g_off[n], end = g_off[n + 1];
    float4 acc = make_float4(0.f, 0.f, 0.f, 0.f);
#pragma unroll 4
    for (int e = beg; e < end; e++) {
        int s = g_esrc[e];
        float4 v = *(const float4*)&g_y[(size_t)s * 128 + lane * 4];
        acc.x += v.x; acc.y += v.y; acc.z += v.z; acc.w += v.w;
    }
    int cnt = end - beg;
    float inv = 1.f / (float)max(cnt, 1);
    float4 z = *(const float4*)&g_z[(size_t)n * 128 + lane * 4];
    float v0 = fmaxf(fmaf(acc.x, inv, z.x), 0.f);
    float v1 = fmaxf(fmaf(acc.y, inv, z.y), 0.f);
    float v2 = fmaxf(fmaf(acc.z, inv, z.z), 0.f);
    float v3 = fmaxf(fmaf(acc.w, inv, z.w), 0.f);

    float s1 = v0 + v1 + v2 + v3;
    float s2 = v0 * v0 + v1 * v1 + v2 * v2 + v3 * v3;
#pragma unroll
    for (int o = 16; o > 0; o >>= 1) {
        s1 += __shfl_xor_sync(0xffffffffu, s1, o);
        s2 += __shfl_xor_sync(0xffffffffu, s2, o);
    }
    float mu = s1 * (1.f / 128.f);
    float var = s2 * (1.f / 128.f) - mu * mu;
    float rs = rsqrtf(var + 1e-5f);
    float4 g4 = *(const float4*)&gamma[lane * 4];
    float4 be = *(const float4*)&beta[lane * 4];
    float4 o;
    o.x = (v0 - mu) * rs * g4.x + be.x;
    o.y = (v1 - mu) * rs * g4.y + be.y;
    o.z = (v2 - mu) * rs * g4.z + be.z;
    o.w = (v3 - mu) * rs * g4.w + be.w;
    *(float4*)&g_h[(size_t)n * 128 + lane * 4] = o;
}

// ---------------- final aggregation (dim 64) ----------------
__global__ void __launch_bounds__(256) k_agg_out(float* __restrict__ out)
{
    int w = threadIdx.x >> 5, lane = threadIdx.x & 31;
    int n = blockIdx.x * 8 + w;
    if (n >= NN) return;
    int beg = g_off[n], end = g_off[n + 1];
    float2 acc = make_float2(0.f, 0.f);
#pragma unroll 4
    for (int e = beg; e < end; e++) {
        int s = g_esrc[e];
        float2 v = *(const float2*)&g_y[(size_t)s * 64 + lane * 2];
        acc.x += v.x; acc.y += v.y;
    }
    int cnt = end - beg;
    float inv = 1.f / (float)max(cnt, 1);
    float2 z = *(const float2*)&g_z[(size_t)n * 64 + lane * 2];
    float2 o;
    o.x = fmaf(acc.x, inv, z.x);
    o.y = fmaf(acc.y, inv, z.y);
    *(float2*)&out[(size_t)n * 64 + lane * 2] = o;
}

// ---------------- launch ----------------
extern "C" void kernel_launch(void* const* d_in, const int* in_sizes, int n_in,
                              void* d_out, int out_size)
{
    const float* x   = (const float*)d_in[0];
    const int*   ei  = (const int*)d_in[1];
    const float* Wl0 = (const float*)d_in[2];
    const float* bl0 = (const float*)d_in[3];
    const float* Wr0 = (const float*)d_in[4];
    const float* Wl1 = (const float*)d_in[5];
    const float* bl1 = (const float*)d_in[6];
    const float* Wr1 = (const float*)d_in[7];
    const float* Wl2 = (const float*)d_in[8];
    const float* bl2 = (const float*)d_in[9];
    const float* Wr2 = (const float*)d_in[10];
    const float* g0  = (const float*)d_in[11];
    const float* b0  = (const float*)d_in[12];
    const float* g1  = (const float*)d_in[13];
    const float* b1  = (const float*)d_in[14];
    float* out = (float*)d_out;

    const int* src = ei;
    const int* dst = ei + EE;

    float* yptr = nullptr; cudaGetSymbolAddress((void**)&yptr, g_y);
    float* zptr = nullptr; cudaGetSymbolAddress((void**)&zptr, g_z);
    float* hptr = nullptr; cudaGetSymbolAddress((void**)&hptr, g_h);
    int*   cptr = nullptr; cudaGetSymbolAddress((void**)&cptr, g_cnt);

    const int NB_N = (NN + 255) / 256;
    const int NB_E = (EE + 255) / 256;
    const int NB_SCAN = (NN + 1023) / 1024;
    const int NB_SORT = (NN + SNODES - 1) / SNODES;
    const int NB_AGG = (NN + 7) / 8;
    dim3 grid_h((NN + 127) / 128, 2);   // layers 0/1: N = 256
    dim3 grid_o((NN + 127) / 128, 1);   // layer 2:  N = 128

    // CSR build (by dst); gemm layer 0 interleaved (independent of CSR)
    cudaMemsetAsync(cptr, 0, NN * sizeof(int));                       // 0
    k_hist<<<NB_E, 256>>>(dst);                                       // 1
    k_scan1<<<NB_SCAN, 1024>>>();                                     // 2
    k_scan2<<<1, 64>>>();                                             // 3
    k_scan3z<<<NB_N, 256>>>();                                        // 4
    k_mmagemm<<<grid_h, 256>>>(x, Wl0, Wr0, bl0, yptr, zptr, 128);    // 5 (ncu target)
    k_scatter<<<NB_E, 256>>>(src, dst);                               // 6
    k_sortseg2<<<NB_SORT, 256>>>();                                   // 7
    k_agg_ln<<<NB_AGG, 256>>>(g0, b0);                                // 8
    // layer 1
    k_mmagemm<<<grid_h, 256>>>(hptr, Wl1, Wr1, bl1, yptr, zptr, 128);
    k_agg_ln<<<NB_AGG, 256>>>(g1, b1);
    // layer 2
    k_mmagemm<<<grid_o, 256>>>(hptr, Wl2, Wr2, bl2, yptr, zptr, 64);
    k_agg_out<<<NB_AGG, 256>>>(out);
}

// round 9
// speedup vs baseline: 1.7189x; 1.0441x over previous
#include <cuda_runtime.h>
#include <cuda_fp16.h>
#include <cstdint>

#define NN 40000
#define EE 640000

// ---------------- scratch (device globals; no allocation) ----------------
__device__ int   g_cnt[NN];
__device__ int   g_off[NN + 1];
__device__ int   g_bsum[64];
__device__ int   g_boff[64];
__device__ int   g_esrc[EE];
__device__ __half g_yh[NN * 128];   // x @ Wl in fp16 (gather source)
__device__ float g_z[NN * 128];     // x @ Wr + b in fp32
__device__ float g_h[NN * 128];

// ---------------- CSR build ----------------
__global__ void k_hist(const int* __restrict__ dst) {
    int e = blockIdx.x * blockDim.x + threadIdx.x;
    if (e < EE) atomicAdd(&g_cnt[dst[e]], 1);
}

__global__ void k_scan1() {
    __shared__ int wsum[32];
    int tid = threadIdx.x, lane = tid & 31, w = tid >> 5;
    int i = blockIdx.x * 1024 + tid;
    int v = (i < NN) ? g_cnt[i] : 0;
    int s = v;
#pragma unroll
    for (int o = 1; o < 32; o <<= 1) {
        int t = __shfl_up_sync(0xffffffffu, s, o);
        if (lane >= o) s += t;
    }
    if (lane == 31) wsum[w] = s;
    __syncthreads();
    if (w == 0) {
        int ws = wsum[lane];
        int ss = ws;
#pragma unroll
        for (int o = 1; o < 32; o <<= 1) {
            int t = __shfl_up_sync(0xffffffffu, ss, o);
            if (lane >= o) ss += t;
        }
        wsum[lane] = ss - ws;
    }
    __syncthreads();
    int incl = s + wsum[w];
    if (i < NN) g_off[i] = incl - v;
    if (tid == 1023) g_bsum[blockIdx.x] = incl;
}

__global__ void k_scan2() {
    __shared__ int sh[64];
    int t = threadIdx.x;
    int nblk = (NN + 1023) / 1024;
    int v = (t < nblk) ? g_bsum[t] : 0;
    sh[t] = v;
    __syncthreads();
    for (int o = 1; o < 64; o <<= 1) {
        int add = (t >= o) ? sh[t - o] : 0;
        __syncthreads();
        sh[t] += add;
        __syncthreads();
    }
    if (t < nblk) g_boff[t] = sh[t] - v;
}

// adds block offsets AND resets g_cnt for the scatter pass
__global__ void k_scan3z() {
    int i = blockIdx.x * blockDim.x + threadIdx.x;
    if (i < NN) {
        g_off[i] += g_boff[i >> 10];
        g_cnt[i] = 0;
    }
    if (i == 0) g_off[NN] = EE;
}

__global__ void k_scatter(const int* __restrict__ src, const int* __restrict__ dst) {
    int e = blockIdx.x * blockDim.x + threadIdx.x;
    if (e < EE) {
        int d = dst[e];
        int p = atomicAdd(&g_cnt[d], 1);
        g_esrc[g_off[d] + p] = src[e];
    }
}

// block-cooperative segment sort: 256 nodes/block staged through smem
#define SNODES 256
#define SCAP   10240   // 40KB of int
__global__ void __launch_bounds__(256) k_sortseg2() {
    __shared__ int buf[SCAP];
    int nb = blockIdx.x * SNODES;
    int ne = min(nb + SNODES, NN);
    int beg = g_off[nb], end = g_off[ne];
    int total = end - beg;
    if (total <= SCAP) {
        for (int i = threadIdx.x; i < total; i += 256) buf[i] = g_esrc[beg + i];
        __syncthreads();
        int n = nb + threadIdx.x;
        if (n < ne) {
            int b = g_off[n] - beg, e = g_off[n + 1] - beg;
            for (int i = b + 1; i < e; i++) {
                int key = buf[i];
                int j = i - 1;
                while (j >= b && buf[j] > key) { buf[j + 1] = buf[j]; j--; }
                buf[j + 1] = key;
            }
        }
        __syncthreads();
        for (int i = threadIdx.x; i < total; i += 256) g_esrc[beg + i] = buf[i];
    } else {  // statistically unreachable fallback: sort in global
        int n = nb + threadIdx.x;
        if (n < ne) {
            int b = g_off[n], e = g_off[n + 1];
            for (int i = b + 1; i < e; i++) {
                int key = g_esrc[i];
                int j = i - 1;
                while (j >= b && g_esrc[j] > key) { g_esrc[j + 1] = g_esrc[j]; j--; }
                g_esrc[j + 1] = key;
            }
        }
    }
}

// ---------------- warp-MMA tf32 dual GEMM, BK=16 double-buffered ----------------
__device__ __forceinline__ uint32_t to_tf32(float x) {
    uint32_t r;
    asm("cvt.rna.tf32.f32 %0, %1;" : "=r"(r) : "f"(x));
    return r;
}

__device__ __forceinline__ void mma_tf32(float* d, const uint32_t* a, const uint32_t* b) {
    asm volatile(
        "mma.sync.aligned.m16n8k8.row.col.f32.tf32.tf32.f32 "
        "{%0,%1,%2,%3}, {%4,%5,%6,%7}, {%8,%9}, {%0,%1,%2,%3};"
        : "+f"(d[0]), "+f"(d[1]), "+f"(d[2]), "+f"(d[3])
        : "r"(a[0]), "r"(a[1]), "r"(a[2]), "r"(a[3]),
          "r"(b[0]), "r"(b[1]));
}

#define ASTR 20     // 16 + pad4 -> conflict-free A frag loads
#define BSTR 136    // 128 + pad8 -> conflict-free B frag loads
#define NSTAGE 8    // 128 / BK

__global__ void __launch_bounds__(256, 2) k_mmagemm(
    const float* __restrict__ X, const float* __restrict__ Wl,
    const float* __restrict__ Wr, const float* __restrict__ bias,
    __half* __restrict__ Y, float* __restrict__ Z, int NOUT)
{
    __shared__ __align__(16) uint32_t As[2][128 * ASTR];  // [m][k]
    __shared__ __align__(16) uint32_t Bs[2][16 * BSTR];   // [k][n]

    int tid = threadIdx.x;
    int wid = tid >> 5, lane = tid & 31;
    int gid = lane >> 2, tig = lane & 3;
    int wm = wid & 3, wn = wid >> 2;   // 4 x 2 warp grid, warp tile 32x64
    int m0 = blockIdx.x * 128;
    int n0 = blockIdx.y * 128;

    int am[2], ak[2], bk[2], bn[2];
    const float* bsrc[2];
#pragma unroll
    for (int it = 0; it < 2; it++) {
        int idx = tid + it * 256;
        am[it] = idx >> 2;
        ak[it] = (idx & 3) * 4;
        bk[it] = idx >> 5;
        int n4 = (idx & 31) * 4;
        int ng = n0 + n4;
        if (ng < NOUT) { bsrc[it] = Wl + ng; bn[it] = n4; }
        else           { bsrc[it] = Wr + (ng - NOUT); bn[it] = n4; }
    }

    float4 ar[2], br[2];
    auto load_stage = [&](int s) {
#pragma unroll
        for (int it = 0; it < 2; it++) {
            int gr = m0 + am[it];
            ar[it] = (gr < NN) ? *(const float4*)&X[(size_t)gr * 128 + s * 16 + ak[it]]
                               : make_float4(0.f, 0.f, 0.f, 0.f);
            br[it] = *(const float4*)&bsrc[it][(size_t)(s * 16 + bk[it]) * NOUT];
        }
    };
    auto store_stage = [&](int buf) {
#pragma unroll
        for (int it = 0; it < 2; it++) {
            uint32_t* p = &As[buf][am[it] * ASTR + ak[it]];
            uint4 v = make_uint4(to_tf32(ar[it].x), to_tf32(ar[it].y),
                                 to_tf32(ar[it].z), to_tf32(ar[it].w));
            *(uint4*)p = v;
            uint32_t* q = &Bs[buf][bk[it] * BSTR + bn[it]];
            uint4 w = make_uint4(to_tf32(br[it].x), to_tf32(br[it].y),
                                 to_tf32(br[it].z), to_tf32(br[it].w));
            *(uint4*)q = w;
        }
    };

    float acc[2][8][4];
#pragma unroll
    for (int mi = 0; mi < 2; mi++)
#pragma unroll
        for (int nf = 0; nf < 8; nf++)
#pragma unroll
            for (int j = 0; j < 4; j++) acc[mi][nf][j] = 0.f;

    load_stage(0);
    store_stage(0);
    __syncthreads();

#pragma unroll
    for (int s = 0; s < NSTAGE; s++) {
        int buf = s & 1;
        if (s + 1 < NSTAGE) load_stage(s + 1);
#pragma unroll
        for (int kk = 0; kk < 16; kk += 8) {
            uint32_t a[2][4];
#pragma unroll
            for (int mi = 0; mi < 2; mi++) {
                int r = wm * 32 + mi * 16;
                a[mi][0] = As[buf][(r + gid) * ASTR + kk + tig];
                a[mi][1] = As[buf][(r + gid + 8) * ASTR + kk + tig];
                a[mi][2] = As[buf][(r + gid) * ASTR + kk + tig + 4];
                a[mi][3] = As[buf][(r + gid + 8) * ASTR + kk + tig + 4];
            }
            uint32_t b[8][2];
#pragma unroll
            for (int nf = 0; nf < 8; nf++) {
                int n = wn * 64 + nf * 8 + gid;
                b[nf][0] = Bs[buf][(kk + tig) * BSTR + n];
                b[nf][1] = Bs[buf][(kk + tig + 4) * BSTR + n];
            }
#pragma unroll
            for (int mi = 0; mi < 2; mi++)
#pragma unroll
                for (int nf = 0; nf < 8; nf++)
                    mma_tf32(acc[mi][nf], a[mi], b[nf]);
        }
        if (s + 1 < NSTAGE) {
            store_stage(buf ^ 1);
            __syncthreads();
        }
    }

    // ---- epilogue: col < NOUT -> Y (fp16) ; else -> Z + bias (fp32) ----
#pragma unroll
    for (int mi = 0; mi < 2; mi++) {
#pragma unroll
        for (int nf = 0; nf < 8; nf++) {
            int col = n0 + wn * 64 + nf * 8 + 2 * tig;
            int r0 = m0 + wm * 32 + mi * 16 + gid;
            int r1 = r0 + 8;
            if (col < NOUT) {
                if (r0 < NN) {
                    __half2 o = __floats2half2_rn(acc[mi][nf][0], acc[mi][nf][1]);
                    *(__half2*)&Y[(size_t)r0 * NOUT + col] = o;
                }
                if (r1 < NN) {
                    __half2 o = __floats2half2_rn(acc[mi][nf][2], acc[mi][nf][3]);
                    *(__half2*)&Y[(size_t)r1 * NOUT + col] = o;
                }
            } else {
                int c = col - NOUT;
                float2 b2 = *(const float2*)&bias[c];
                if (r0 < NN) { float2 o = {acc[mi][nf][0] + b2.x, acc[mi][nf][1] + b2.y};
                               *(float2*)&Z[(size_t)r0 * NOUT + c] = o; }
                if (r1 < NN) { float2 o = {acc[mi][nf][2] + b2.x, acc[mi][nf][3] + b2.y};
                               *(float2*)&Z[(size_t)r1 * NOUT + c] = o; }
            }
        }
    }
}

// ---------------- aggregation + relu + LayerNorm (dim 128, fp16 gather) ----------------
__global__ void __launch_bounds__(256) k_agg_ln(
    const float* __restrict__ gamma, const float* __restrict__ beta)
{
    int w = threadIdx.x >> 5, lane = threadIdx.x & 31;
    int n = blockIdx.x * 8 + w;
    if (n >= NN) return;
    int beg = g_off[n], end = g_off[n + 1];
    float4 acc = make_float4(0.f, 0.f, 0.f, 0.f);
#pragma unroll 4
    for (int e = beg; e < end; e++) {
        int s = g_esrc[e];
        uint2 d = *(const uint2*)&g_yh[(size_t)s * 128 + lane * 4];
        __half2 p0 = *reinterpret_cast<__half2*>(&d.x);
        __half2 p1 = *reinterpret_cast<__half2*>(&d.y);
        float2 f0 = __half22float2(p0);
        float2 f1 = __half22float2(p1);
        acc.x += f0.x; acc.y += f0.y; acc.z += f1.x; acc.w += f1.y;
    }
    int cnt = end - beg;
    float inv = 1.f / (float)max(cnt, 1);
    float4 z = *(const float4*)&g_z[(size_t)n * 128 + lane * 4];
    float v0 = fmaxf(fmaf(acc.x, inv, z.x), 0.f);
    float v1 = fmaxf(fmaf(acc.y, inv, z.y), 0.f);
    float v2 = fmaxf(fmaf(acc.z, inv, z.z), 0.f);
    float v3 = fmaxf(fmaf(acc.w, inv, z.w), 0.f);

    float s1 = v0 + v1 + v2 + v3;
    float s2 = v0 * v0 + v1 * v1 + v2 * v2 + v3 * v3;
#pragma unroll
    for (int o = 16; o > 0; o >>= 1) {
        s1 += __shfl_xor_sync(0xffffffffu, s1, o);
        s2 += __shfl_xor_sync(0xffffffffu, s2, o);
    }
    float mu = s1 * (1.f / 128.f);
    float var = s2 * (1.f / 128.f) - mu * mu;
    float rs = rsqrtf(var + 1e-5f);
    float4 g4 = *(const float4*)&gamma[lane * 4];
    float4 be = *(const float4*)&beta[lane * 4];
    float4 o;
    o.x = (v0 - mu) * rs * g4.x + be.x;
    o.y = (v1 - mu) * rs * g4.y + be.y;
    o.z = (v2 - mu) * rs * g4.z + be.z;
    o.w = (v3 - mu) * rs * g4.w + be.w;
    *(float4*)&g_h[(size_t)n * 128 + lane * 4] = o;
}

// ---------------- final aggregation (dim 64, fp16 gather) ----------------
__global__ void __launch_bounds__(256) k_agg_out(float* __restrict__ out)
{
    int w = threadIdx.x >> 5, lane = threadIdx.x & 31;
    int n = blockIdx.x * 8 + w;
    if (n >= NN) return;
    int beg = g_off[n], end = g_off[n + 1];
    float2 acc = make_float2(0.f, 0.f);
#pragma unroll 4
    for (int e = beg; e < end; e++) {
        int s = g_esrc[e];
        uint d = *(const uint*)&g_yh[(size_t)s * 64 + lane * 2];
        __half2 p = *reinterpret_cast<__half2*>(&d);
        float2 f = __half22float2(p);
        acc.x += f.x; acc.y += f.y;
    }
    int cnt = end - beg;
    float inv = 1.f / (float)max(cnt, 1);
    float2 z = *(const float2*)&g_z[(size_t)n * 64 + lane * 2];
    float2 o;
    o.x = fmaf(acc.x, inv, z.x);
    o.y = fmaf(acc.y, inv, z.y);
    *(float2*)&out[(size_t)n * 64 + lane * 2] = o;
}

// ---------------- launch ----------------
extern "C" void kernel_launch(void* const* d_in, const int* in_sizes, int n_in,
                              void* d_out, int out_size)
{
    const float* x   = (const float*)d_in[0];
    const int*   ei  = (const int*)d_in[1];
    const float* Wl0 = (const float*)d_in[2];
    const float* bl0 = (const float*)d_in[3];
    const float* Wr0 = (const float*)d_in[4];
    const float* Wl1 = (const float*)d_in[5];
    const float* bl1 = (const float*)d_in[6];
    const float* Wr1 = (const float*)d_in[7];
    const float* Wl2 = (const float*)d_in[8];
    const float* bl2 = (const float*)d_in[9];
    const float* Wr2 = (const float*)d_in[10];
    const float* g0  = (const float*)d_in[11];
    const float* b0  = (const float*)d_in[12];
    const float* g1  = (const float*)d_in[13];
    const float* b1  = (const float*)d_in[14];
    float* out = (float*)d_out;

    const int* src = ei;
    const int* dst = ei + EE;

    __half* yptr = nullptr; cudaGetSymbolAddress((void**)&yptr, g_yh);
    float* zptr = nullptr; cudaGetSymbolAddress((void**)&zptr, g_z);
    float* hptr = nullptr; cudaGetSymbolAddress((void**)&hptr, g_h);
    int*   cptr = nullptr; cudaGetSymbolAddress((void**)&cptr, g_cnt);

    const int NB_N = (NN + 255) / 256;
    const int NB_E = (EE + 255) / 256;
    const int NB_SCAN = (NN + 1023) / 1024;
    const int NB_SORT = (NN + SNODES - 1) / SNODES;
    const int NB_AGG = (NN + 7) / 8;
    dim3 grid_h((NN + 127) / 128, 2);   // layers 0/1: N = 256
    dim3 grid_o((NN + 127) / 128, 1);   // layer 2:  N = 128

    // kernel launch index 3 (0-based, memset excluded) = k_mmagemm -> ncu target
    cudaMemsetAsync(cptr, 0, NN * sizeof(int));
    k_hist<<<NB_E, 256>>>(dst);                                       // 0
    k_scan1<<<NB_SCAN, 1024>>>();                                     // 1
    k_scan2<<<1, 64>>>();                                             // 2
    k_mmagemm<<<grid_h, 256>>>(x, Wl0, Wr0, bl0, yptr, zptr, 128);    // 3 (ncu)
    k_scan3z<<<NB_N, 256>>>();                                        // 4
    k_scatter<<<NB_E, 256>>>(src, dst);                               // 5
    k_sortseg2<<<NB_SORT, 256>>>();                                   // 6
    k_agg_ln<<<NB_AGG, 256>>>(g0, b0);                                // 7
    // layer 1
    k_mmagemm<<<grid_h, 256>>>(hptr, Wl1, Wr1, bl1, yptr, zptr, 128);
    k_agg_ln<<<NB_AGG, 256>>>(g1, b1);
    // layer 2
    k_mmagemm<<<grid_o, 256>>>(hptr, Wl2, Wr2, bl2, yptr, zptr, 64);
    k_agg_out<<<NB_AGG, 256>>>(out);
}

// round 12
// speedup vs baseline: 1.8582x; 1.0810x over previous
#include <cuda_runtime.h>
#include <cuda_fp16.h>
#include <cstdint>

#define NN 40000
#define EE 640000

// ---------------- scratch (device globals; no allocation) ----------------
__device__ int   g_cnt[NN];
__device__ int   g_off[NN + 1];
__device__ int   g_bsum[64];
__device__ int   g_boff[64];
__device__ int   g_esrc[EE];
__device__ __half g_yh[NN * 128];   // x @ Wl in fp16 (gather source)
__device__ float g_z[NN * 128];     // x @ Wr + b in fp32
__device__ float g_h[NN * 128];

// ---------------- CSR build ----------------
__global__ void k_hist(const int* __restrict__ dst) {
    int e = blockIdx.x * blockDim.x + threadIdx.x;
    if (e < EE) atomicAdd(&g_cnt[dst[e]], 1);
}

__global__ void k_scan1() {
    __shared__ int wsum[32];
    int tid = threadIdx.x, lane = tid & 31, w = tid >> 5;
    int i = blockIdx.x * 1024 + tid;
    int v = (i < NN) ? g_cnt[i] : 0;
    int s = v;
#pragma unroll
    for (int o = 1; o < 32; o <<= 1) {
        int t = __shfl_up_sync(0xffffffffu, s, o);
        if (lane >= o) s += t;
    }
    if (lane == 31) wsum[w] = s;
    __syncthreads();
    if (w == 0) {
        int ws = wsum[lane];
        int ss = ws;
#pragma unroll
        for (int o = 1; o < 32; o <<= 1) {
            int t = __shfl_up_sync(0xffffffffu, ss, o);
            if (lane >= o) ss += t;
        }
        wsum[lane] = ss - ws;
    }
    __syncthreads();
    int incl = s + wsum[w];
    if (i < NN) g_off[i] = incl - v;
    if (tid == 1023) g_bsum[blockIdx.x] = incl;
}

__global__ void k_scan2() {
    __shared__ int sh[64];
    int t = threadIdx.x;
    int nblk = (NN + 1023) / 1024;
    int v = (t < nblk) ? g_bsum[t] : 0;
    sh[t] = v;
    __syncthreads();
    for (int o = 1; o < 64; o <<= 1) {
        int add = (t >= o) ? sh[t - o] : 0;
        __syncthreads();
        sh[t] += add;
        __syncthreads();
    }
    if (t < nblk) g_boff[t] = sh[t] - v;
}

// adds block offsets AND resets g_cnt for the scatter pass
__global__ void k_scan3z() {
    int i = blockIdx.x * blockDim.x + threadIdx.x;
    if (i < NN) {
        g_off[i] += g_boff[i >> 10];
        g_cnt[i] = 0;
    }
    if (i == 0) g_off[NN] = EE;
}

__global__ void k_scatter(const int* __restrict__ src, const int* __restrict__ dst) {
    int e = blockIdx.x * blockDim.x + threadIdx.x;
    if (e < EE) {
        int d = dst[e];
        int p = atomicAdd(&g_cnt[d], 1);
        g_esrc[g_off[d] + p] = src[e];
    }
}

// block-cooperative segment sort: 256 nodes/block staged through smem
#define SNODES 256
#define SCAP   10240   // 40KB of int
__global__ void __launch_bounds__(256) k_sortseg2() {
    __shared__ int buf[SCAP];
    int nb = blockIdx.x * SNODES;
    int ne = min(nb + SNODES, NN);
    int beg = g_off[nb], end = g_off[ne];
    int total = end - beg;
    if (total <= SCAP) {
        for (int i = threadIdx.x; i < total; i += 256) buf[i] = g_esrc[beg + i];
        __syncthreads();
        int n = nb + threadIdx.x;
        if (n < ne) {
            int b = g_off[n] - beg, e = g_off[n + 1] - beg;
            for (int i = b + 1; i < e; i++) {
                int key = buf[i];
                int j = i - 1;
                while (j >= b && buf[j] > key) { buf[j + 1] = buf[j]; j--; }
                buf[j + 1] = key;
            }
        }
        __syncthreads();
        for (int i = threadIdx.x; i < total; i += 256) g_esrc[beg + i] = buf[i];
    } else {  // statistically unreachable fallback: sort in global
        int n = nb + threadIdx.x;
        if (n < ne) {
            int b = g_off[n], e = g_off[n + 1];
            for (int i = b + 1; i < e; i++) {
                int key = g_esrc[i];
                int j = i - 1;
                while (j >= b && g_esrc[j] > key) { g_esrc[j + 1] = g_esrc[j]; j--; }
                g_esrc[j + 1] = key;
            }
        }
    }
}

// ---------------- fp16 m16n8k16 dual GEMM, BK=16 double-buffered ----------------
__device__ __forceinline__ uint32_t smem_u32(const void* p) {
    return (uint32_t)__cvta_generic_to_shared(p);
}

__device__ __forceinline__ void ldmatrix_x4(uint32_t* a, uint32_t addr) {
    asm volatile("ldmatrix.sync.aligned.m8n8.x4.shared.b16 {%0,%1,%2,%3}, [%4];"
                 : "=r"(a[0]), "=r"(a[1]), "=r"(a[2]), "=r"(a[3]) : "r"(addr));
}
__device__ __forceinline__ void ldmatrix_x2_t(uint32_t& b0, uint32_t& b1, uint32_t addr) {
    asm volatile("ldmatrix.sync.aligned.m8n8.x2.trans.shared.b16 {%0,%1}, [%2];"
                 : "=r"(b0), "=r"(b1) : "r"(addr));
}
__device__ __forceinline__ void mma_f16(float* d, const uint32_t* a, const uint32_t* b) {
    asm volatile(
        "mma.sync.aligned.m16n8k16.row.col.f32.f16.f16.f32 "
        "{%0,%1,%2,%3}, {%4,%5,%6,%7}, {%8,%9}, {%0,%1,%2,%3};"
        : "+f"(d[0]), "+f"(d[1]), "+f"(d[2]), "+f"(d[3])
        : "r"(a[0]), "r"(a[1]), "r"(a[2]), "r"(a[3]),
          "r"(b[0]), "r"(b[1]));
}

#define ASTRH 24    // halves per A row (16 data + 8 pad); 48B -> ldmatrix conflict-free
#define BSTRH 136   // halves per B k-row (128 + 8); 272B -> conflict-free
#define NSTAGE 8    // 128 / 16

__global__ void __launch_bounds__(256, 2) k_mmagemm(
    const float* __restrict__ X, const float* __restrict__ Wl,
    const float* __restrict__ Wr, const float* __restrict__ bias,
    __half* __restrict__ Y, float* __restrict__ Z, int NOUT)
{
    __shared__ __align__(16) __half Ah[2][128 * ASTRH];  // [m][k]
    __shared__ __align__(16) __half Bh[2][16 * BSTRH];   // [k][n]

    int tid = threadIdx.x;
    int wid = tid >> 5, lane = tid & 31;
    int gid = lane >> 2, tig = lane & 3;
    int wm = wid & 3, wn = wid >> 2;   // 4 x 2 warp grid, warp tile 32x64
    int m0 = blockIdx.x * 128;
    int n0 = blockIdx.y * 128;

    // per-stage load geometry (2 float4 each for A and B per thread)
    int am[2], ak[2], bk[2], bn[2];
    const float* bsrc[2];
#pragma unroll
    for (int it = 0; it < 2; it++) {
        int idx = tid + it * 256;
        am[it] = idx >> 2;            // A: m row, 4 k-floats each
        ak[it] = (idx & 3) * 4;
        bk[it] = idx >> 5;            // B: k row, 4 n-floats each
        int n4 = (idx & 31) * 4;
        int ng = n0 + n4;
        if (ng < NOUT) { bsrc[it] = Wl + ng; bn[it] = n4; }
        else           { bsrc[it] = Wr + (ng - NOUT); bn[it] = n4; }
    }

    float4 ar[2], br[2];
    auto load_stage = [&](int s) {
#pragma unroll
        for (int it = 0; it < 2; it++) {
            int gr = m0 + am[it];
            ar[it] = (gr < NN) ? *(const float4*)&X[(size_t)gr * 128 + s * 16 + ak[it]]
                               : make_float4(0.f, 0.f, 0.f, 0.f);
            br[it] = *(const float4*)&bsrc[it][(size_t)(s * 16 + bk[it]) * NOUT];
        }
    };
    auto store_stage = [&](int buf) {
#pragma unroll
        for (int it = 0; it < 2; it++) {
            __half2 a0 = __floats2half2_rn(ar[it].x, ar[it].y);
            __half2 a1 = __floats2half2_rn(ar[it].z, ar[it].w);
            *(uint2*)&Ah[buf][am[it] * ASTRH + ak[it]] =
                make_uint2(*(uint32_t*)&a0, *(uint32_t*)&a1);
            __half2 b0 = __floats2half2_rn(br[it].x, br[it].y);
            __half2 b1 = __floats2half2_rn(br[it].z, br[it].w);
            *(uint2*)&Bh[buf][bk[it] * BSTRH + bn[it]] =
                make_uint2(*(uint32_t*)&b0, *(uint32_t*)&b1);
        }
    };

    float acc[2][8][4];
#pragma unroll
    for (int mi = 0; mi < 2; mi++)
#pragma unroll
        for (int nf = 0; nf < 8; nf++)
#pragma unroll
            for (int j = 0; j < 4; j++) acc[mi][nf][j] = 0.f;

    // ldmatrix lane addressing (constant across stages except buffer base)
    int a_row = (lane & 15);           // row within 16-row tile
    int a_col = (lane >> 4) << 3;      // 0 or 8 halves
    int b_row = (lane & 15);           // k row (lanes 16-31 unused by x2)

    load_stage(0);
    store_stage(0);
    __syncthreads();

#pragma unroll
    for (int s = 0; s < NSTAGE; s++) {
        int buf = s & 1;
        if (s + 1 < NSTAGE) load_stage(s + 1);

        uint32_t a[2][4];
#pragma unroll
        for (int mi = 0; mi < 2; mi++) {
            int r = wm * 32 + mi * 16;
            uint32_t addr = smem_u32(&Ah[buf][(r + a_row) * ASTRH + a_col]);
            ldmatrix_x4(a[mi], addr);
        }
        uint32_t b[8][2];
#pragma unroll
        for (int nf = 0; nf < 8; nf++) {
            int n = wn * 64 + nf * 8;
            uint32_t addr = smem_u32(&Bh[buf][b_row * BSTRH + n]);
            ldmatrix_x2_t(b[nf][0], b[nf][1], addr);
        }
#pragma unroll
        for (int mi = 0; mi < 2; mi++)
#pragma unroll
            for (int nf = 0; nf < 8; nf++)
                mma_f16(acc[mi][nf], a[mi], b[nf]);

        if (s + 1 < NSTAGE) {
            store_stage(buf ^ 1);
            __syncthreads();
        }
    }

    // ---- epilogue: col < NOUT -> Y (fp16) ; else -> Z + bias (fp32) ----
#pragma unroll
    for (int mi = 0; mi < 2; mi++) {
#pragma unroll
        for (int nf = 0; nf < 8; nf++) {
            int col = n0 + wn * 64 + nf * 8 + 2 * tig;
            int r0 = m0 + wm * 32 + mi * 16 + gid;
            int r1 = r0 + 8;
            if (col < NOUT) {
                if (r0 < NN) {
                    __half2 o = __floats2half2_rn(acc[mi][nf][0], acc[mi][nf][1]);
                    *(__half2*)&Y[(size_t)r0 * NOUT + col] = o;
                }
                if (r1 < NN) {
                    __half2 o = __floats2half2_rn(acc[mi][nf][2], acc[mi][nf][3]);
                    *(__half2*)&Y[(size_t)r1 * NOUT + col] = o;
                }
            } else {
                int c = col - NOUT;
                float2 b2 = *(const float2*)&bias[c];
                if (r0 < NN) { float2 o = {acc[mi][nf][0] + b2.x, acc[mi][nf][1] + b2.y};
                               *(float2*)&Z[(size_t)r0 * NOUT + c] = o; }
                if (r1 < NN) { float2 o = {acc[mi][nf][2] + b2.x, acc[mi][nf][3] + b2.y};
                               *(float2*)&Z[(size_t)r1 * NOUT + c] = o; }
            }
        }
    }
}

// ---------------- aggregation + relu + LayerNorm (dim 128, fp16 gather) ----------------
__global__ void __launch_bounds__(256) k_agg_ln(
    const float* __restrict__ gamma, const float* __restrict__ beta)
{
    int w = threadIdx.x >> 5, lane = threadIdx.x & 31;
    int n = blockIdx.x * 8 + w;
    if (n >= NN) return;
    int beg = g_off[n], end = g_off[n + 1];
    float4 acc = make_float4(0.f, 0.f, 0.f, 0.f);
#pragma unroll 4
    for (int e = beg; e < end; e++) {
        int s = g_esrc[e];
        uint2 d = *(const uint2*)&g_yh[(size_t)s * 128 + lane * 4];
        __half2 p0 = *reinterpret_cast<__half2*>(&d.x);
        __half2 p1 = *reinterpret_cast<__half2*>(&d.y);
        float2 f0 = __half22float2(p0);
        float2 f1 = __half22float2(p1);
        acc.x += f0.x; acc.y += f0.y; acc.z += f1.x; acc.w += f1.y;
    }
    int cnt = end - beg;
    float inv = 1.f / (float)max(cnt, 1);
    float4 z = *(const float4*)&g_z[(size_t)n * 128 + lane * 4];
    float v0 = fmaxf(fmaf(acc.x, inv, z.x), 0.f);
    float v1 = fmaxf(fmaf(acc.y, inv, z.y), 0.f);
    float v2 = fmaxf(fmaf(acc.z, inv, z.z), 0.f);
    float v3 = fmaxf(fmaf(acc.w, inv, z.w), 0.f);

    float s1 = v0 + v1 + v2 + v3;
    float s2 = v0 * v0 + v1 * v1 + v2 * v2 + v3 * v3;
#pragma unroll
    for (int o = 16; o > 0; o >>= 1) {
        s1 += __shfl_xor_sync(0xffffffffu, s1, o);
        s2 += __shfl_xor_sync(0xffffffffu, s2, o);
    }
    float mu = s1 * (1.f / 128.f);
    float var = s2 * (1.f / 128.f) - mu * mu;
    float rs = rsqrtf(var + 1e-5f);
    float4 g4 = *(const float4*)&gamma[lane * 4];
    float4 be = *(const float4*)&beta[lane * 4];
    float4 o;
    o.x = (v0 - mu) * rs * g4.x + be.x;
    o.y = (v1 - mu) * rs * g4.y + be.y;
    o.z = (v2 - mu) * rs * g4.z + be.z;
    o.w = (v3 - mu) * rs * g4.w + be.w;
    *(float4*)&g_h[(size_t)n * 128 + lane * 4] = o;
}

// ---------------- final aggregation (dim 64, fp16 gather) ----------------
__global__ void __launch_bounds__(256) k_agg_out(float* __restrict__ out)
{
    int w = threadIdx.x >> 5, lane = threadIdx.x & 31;
    int n = blockIdx.x * 8 + w;
    if (n >= NN) return;
    int beg = g_off[n], end = g_off[n + 1];
    float2 acc = make_float2(0.f, 0.f);
#pragma unroll 4
    for (int e = beg; e < end; e++) {
        int s = g_esrc[e];
        uint d = *(const uint*)&g_yh[(size_t)s * 64 + lane * 2];
        __half2 p = *reinterpret_cast<__half2*>(&d);
        float2 f = __half22float2(p);
        acc.x += f.x; acc.y += f.y;
    }
    int cnt = end - beg;
    float inv = 1.f / (float)max(cnt, 1);
    float2 z = *(const float2*)&g_z[(size_t)n * 64 + lane * 2];
    float2 o;
    o.x = fmaf(acc.x, inv, z.x);
    o.y = fmaf(acc.y, inv, z.y);
    *(float2*)&out[(size_t)n * 64 + lane * 2] = o;
}

// ---------------- launch ----------------
extern "C" void kernel_launch(void* const* d_in, const int* in_sizes, int n_in,
                              void* d_out, int out_size)
{
    const float* x   = (const float*)d_in[0];
    const int*   ei  = (const int*)d_in[1];
    const float* Wl0 = (const float*)d_in[2];
    const float* bl0 = (const float*)d_in[3];
    const float* Wr0 = (const float*)d_in[4];
    const float* Wl1 = (const float*)d_in[5];
    const float* bl1 = (const float*)d_in[6];
    const float* Wr1 = (const float*)d_in[7];
    const float* Wl2 = (const float*)d_in[8];
    const float* bl2 = (const float*)d_in[9];
    const float* Wr2 = (const float*)d_in[10];
    const float* g0  = (const float*)d_in[11];
    const float* b0  = (const float*)d_in[12];
    const float* g1  = (const float*)d_in[13];
    const float* b1  = (const float*)d_in[14];
    float* out = (float*)d_out;

    const int* src = ei;
    const int* dst = ei + EE;

    __half* yptr = nullptr; cudaGetSymbolAddress((void**)&yptr, g_yh);
    float* zptr = nullptr; cudaGetSymbolAddress((void**)&zptr, g_z);
    float* hptr = nullptr; cudaGetSymbolAddress((void**)&hptr, g_h);
    int*   cptr = nullptr; cudaGetSymbolAddress((void**)&cptr, g_cnt);

    const int NB_N = (NN + 255) / 256;
    const int NB_E = (EE + 255) / 256;
    const int NB_SCAN = (NN + 1023) / 1024;
    const int NB_SORT = (NN + SNODES - 1) / SNODES;
    const int NB_AGG = (NN + 7) / 8;
    dim3 grid_h((NN + 127) / 128, 2);   // layers 0/1: N = 256
    dim3 grid_o((NN + 127) / 128, 1);   // layer 2:  N = 128

    // kernel launch index 3 (0-based, memset excluded) = k_mmagemm -> ncu target
    cudaMemsetAsync(cptr, 0, NN * sizeof(int));
    k_hist<<<NB_E, 256>>>(dst);                                       // 0
    k_scan1<<<NB_SCAN, 1024>>>();                                     // 1
    k_scan2<<<1, 64>>>();                                             // 2
    k_mmagemm<<<grid_h, 256>>>(x, Wl0, Wr0, bl0, yptr, zptr, 128);    // 3 (ncu)
    k_scan3z<<<NB_N, 256>>>();                                        // 4
    k_scatter<<<NB_E, 256>>>(src, dst);                               // 5
    k_sortseg2<<<NB_SORT, 256>>>();                                   // 6
    k_agg_ln<<<NB_AGG, 256>>>(g0, b0);                                // 7
    // layer 1
    k_mmagemm<<<grid_h, 256>>>(hptr, Wl1, Wr1, bl1, yptr, zptr, 128);
    k_agg_ln<<<NB_AGG, 256>>>(g1, b1);
    // layer 2
    k_mmagemm<<<grid_o, 256>>>(hptr, Wl2, Wr2, bl2, yptr, zptr, 64);
    k_agg_out<<<NB_AGG, 256>>>(out);
}